// round 14
// baseline (speedup 1.0000x reference)
#include <cuda_runtime.h>
#include <cuda_fp16.h>
#include <math.h>
#include <stdint.h>

// Problem constants
#define BB 8
#define LL 1024
#define DD 256
#define FF 11
#define TEMP_INV (1.0f/16.0f)
#define LN_EPS 1e-6f

// GEMM config: 128x128 CTA tile, K-slab 64, 16 warps (4m x 4n), warp tile 32x32
// fp16 2-pass: D = aH*bH + aH*bL  (dropped aL*b ~ 2^-11)
#define SLAB 64
#define TB 16384                // one 128x64 fp16 tile (128 rows x 128B)
#define BUFB (3*TB)             // AH BH BL = 48KB
#define SMEM_DYN (2*BUFB)       // 98304 (double buffered)
#define NT 512                  // threads per CTA

// ---------------------------------------------------------------------------
// Scratch
// ---------------------------------------------------------------------------
__device__ float g_qp [BB*LL*DD];
__device__ float g_kp [BB*LL*DD];
__device__ float g_q2t[BB*LL*DD];   // [b][d][t]
__device__ float g_k2t[BB*LL*DD];
__device__ float g_vpt[BB*LL*DD];
__device__ float g_q2f[BB*LL*DD];
__device__ float g_k2f[BB*LL*DD];
__device__ float g_ov [BB*LL*DD];
__device__ float g_fc [BB*LL*DD];
__device__ float g_fa [(size_t)BB*LL*LL];
__device__ float g_attn_scratch[(size_t)BB*LL*LL];

// ---------------------------------------------------------------------------
// Helpers
// ---------------------------------------------------------------------------
__device__ __forceinline__ uint32_t smem_u32(const void* p) {
    uint32_t a;
    asm("{ .reg .u64 t; cvta.to.shared.u64 t, %1; cvt.u32.u64 %0, t; }"
        : "=r"(a) : "l"(p));
    return a;
}

__device__ __forceinline__ void ldsm_x4(uint32_t* r, uint32_t a) {
    asm volatile("ldmatrix.sync.aligned.m8n8.x4.shared.b16 {%0,%1,%2,%3}, [%4];"
        : "=r"(r[0]), "=r"(r[1]), "=r"(r[2]), "=r"(r[3]) : "r"(a));
}

__device__ __forceinline__ void mma16816(float* c, const uint32_t* a, const uint32_t* b) {
    asm volatile("mma.sync.aligned.m16n8k16.row.col.f32.f16.f16.f32 "
        "{%0,%1,%2,%3}, {%4,%5,%6,%7}, {%8,%9}, {%0,%1,%2,%3};"
        : "+f"(c[0]), "+f"(c[1]), "+f"(c[2]), "+f"(c[3])
        : "r"(a[0]), "r"(a[1]), "r"(a[2]), "r"(a[3]), "r"(b[0]), "r"(b[1]));
}

__device__ __forceinline__ uint32_t pack_h2(float x, float y) {
    __half2 h = __floats2half2_rn(x, y);
    return *(uint32_t*)&h;
}

// Load a 128x64 fp32 tile into registers (4 float4 per thread, 512 threads).
__device__ __forceinline__
void ld_tile(const float* __restrict__ src, int r0, int ld, int k0,
             float4* v, int tid)
{
    #pragma unroll
    for (int i = 0; i < 4; i++) {
        int f = tid + (i << 9);
        int row = f >> 4, c4 = f & 15;
        v[i] = *(const float4*)(src + (size_t)(r0 + row) * ld + k0 + (c4 << 2));
    }
}

// A tile: fp16 hi only, SW128-swizzled.
__device__ __forceinline__
void st_tile_a(const float4* v, char* smem, uint32_t off, int tid)
{
    #pragma unroll
    for (int i = 0; i < 4; i++) {
        int f = tid + (i << 9);
        int row = f >> 4, c4 = f & 15;
        float4 a = v[i];
        uint32_t byte = (row << 7) + (c4 << 3);
        uint32_t sw = byte ^ ((byte >> 3) & 0x70);
        *(uint2*)(smem + off + sw) = make_uint2(pack_h2(a.x, a.y), pack_h2(a.z, a.w));
    }
}

// B tile: fp16 hi + lo (residual), SW128-swizzled.
__device__ __forceinline__
void st_tile_b(const float4* v, char* smem, uint32_t hiOff, uint32_t loOff, int tid)
{
    #pragma unroll
    for (int i = 0; i < 4; i++) {
        int f = tid + (i << 9);
        int row = f >> 4, c4 = f & 15;
        float4 a = v[i];
        __half2 h01 = __floats2half2_rn(a.x, a.y);
        __half2 h23 = __floats2half2_rn(a.z, a.w);
        float rx = a.x - __low2float(h01);
        float ry = a.y - __high2float(h01);
        float rz = a.z - __low2float(h23);
        float rw = a.w - __high2float(h23);
        uint32_t byte = (row << 7) + (c4 << 3);
        uint32_t sw = byte ^ ((byte >> 3) & 0x70);
        *(uint2*)(smem + hiOff + sw) = make_uint2(*(uint32_t*)&h01, *(uint32_t*)&h23);
        *(uint2*)(smem + loOff + sw) = make_uint2(pack_h2(rx, ry), pack_h2(rz, rw));
    }
}

// ---------------------------------------------------------------------------
// fp16x2 mma.sync GEMM body. NT: C[m,n] = sum_k A[m,k]*B[n,k] over
// (A1,B1,kext1,ld1) then (A2,B2,kext2,ld2). kext may be < ld (masked K).
// MODE: 0 plain, 1 +add residual, 2 tanh(acc/16) w/ col mask
// ---------------------------------------------------------------------------
template<int MODE>
__device__ __forceinline__
void tc_body(const float* __restrict__ A1, const float* __restrict__ B1,
             int k1, int ld1,
             const float* __restrict__ A2, const float* __restrict__ B2,
             int k2, int ld2,
             float* __restrict__ C, const float* __restrict__ add,
             int ldc, int len, int m0, int n0)
{
    extern __shared__ char smem[];
    const uint32_t sb = smem_u32(smem);
    const int tid = threadIdx.x;
    const int lane = tid & 31, wid = tid >> 5;
    const int wm = wid & 3, wn = wid >> 2;

    float acc[2][4][4] = {};

    // ldmatrix lane addressing (128B rows, SW128-style XOR)
    const int a_row = wm * 32 + (lane & 15);
    const uint32_t a_colp = (lane >> 4) << 4;
    const uint32_t a_xor = (uint32_t)(a_row & 7) << 4;
    const int b_row = wn * 32 + ((lane >> 4) << 3) + (lane & 7);
    const uint32_t b_colp = ((lane >> 3) & 1) << 4;
    const uint32_t b_xor = (uint32_t)(b_row & 7) << 4;

    const int n1 = k1 / SLAB;
    const int nslabs = n1 + (A2 ? k2 / SLAB : 0);

    float4 av[4], bv[4];
    // prologue: slab 0
    ld_tile(A1, m0, ld1, 0, av, tid);
    ld_tile(B1, n0, ld1, 0, bv, tid);
    st_tile_a(av, smem, 0, tid);
    st_tile_b(bv, smem, TB, 2*TB, tid);
    __syncthreads();

    for (int s = 0; s < nslabs; s++) {
        const uint32_t bo = (s & 1) * BUFB;
        const uint32_t bn = bo ^ BUFB;
        const bool has = (s + 1) < nslabs;
        const float *An = A1, *Bn = B1; int ldn = ld1, k0n = 0;
        if (has) {
            int sn = s + 1;
            if (sn < n1) { An = A1; Bn = B1; ldn = ld1; k0n = sn * SLAB; }
            else         { An = A2; Bn = B2; ldn = ld2; k0n = (sn - n1) * SLAB; }
        }

        #pragma unroll
        for (int kk = 0; kk < 4; kk++) {
            if (kk == 0 && has) ld_tile(An, m0, ldn, k0n, av, tid);
            if (kk == 2 && has) {
                st_tile_a(av, smem, bn, tid);
                ld_tile(Bn, n0, ldn, k0n, bv, tid);
            }
            if (kk == 3 && has) st_tile_b(bv, smem, bn + TB, bn + 2*TB, tid);

            const uint32_t kb = kk << 5;
            uint32_t bH[8], bL[8];
            {
                uint32_t r = (uint32_t)b_row << 7;
                uint32_t c = (kb + b_colp) ^ b_xor;
                ldsm_x4(bH + 0, sb + bo + TB + r + c);
                ldsm_x4(bH + 4, sb + bo + TB + r + 2048 + c);
                ldsm_x4(bL + 0, sb + bo + 2*TB + r + c);
                ldsm_x4(bL + 4, sb + bo + 2*TB + r + 2048 + c);
            }
            #pragma unroll
            for (int mt = 0; mt < 2; mt++) {
                uint32_t aH[4];
                uint32_t r = (uint32_t)(a_row + mt*16) << 7;
                uint32_t c = (kb + a_colp) ^ a_xor;
                ldsm_x4(aH, sb + bo + r + c);
                #pragma unroll
                for (int nt = 0; nt < 4; nt++) {
                    mma16816(acc[mt][nt], aH, bH + nt*2);
                    mma16816(acc[mt][nt], aH, bL + nt*2);
                }
            }
        }
        if (has) __syncthreads();
    }

    // epilogue
    const int mg = m0 + wm * 32;
    const int ng = n0 + wn * 32;
    const int rq = lane >> 2;
    const int cq = (lane & 3) << 1;
    #pragma unroll
    for (int mt = 0; mt < 2; mt++) {
        #pragma unroll
        for (int nt = 0; nt < 4; nt++) {
            const float* a4 = acc[mt][nt];
            const int r0 = mg + mt*16 + rq, r1 = r0 + 8;
            const int c0 = ng + nt*8 + cq;
            if (MODE == 0) {
                *(float2*)(C + (size_t)r0*ldc + c0) = make_float2(a4[0], a4[1]);
                *(float2*)(C + (size_t)r1*ldc + c0) = make_float2(a4[2], a4[3]);
            } else if (MODE == 1) {
                float2 x0 = *(const float2*)(add + (size_t)r0*ldc + c0);
                float2 x1 = *(const float2*)(add + (size_t)r1*ldc + c0);
                *(float2*)(C + (size_t)r0*ldc + c0) = make_float2(a4[0]+x0.x, a4[1]+x0.y);
                *(float2*)(C + (size_t)r1*ldc + c0) = make_float2(a4[2]+x1.x, a4[3]+x1.y);
            } else {
                float2 v0, v1;
                v0.x = (c0   < len) ? tanhf(a4[0]*TEMP_INV) : 0.f;
                v0.y = (c0+1 < len) ? tanhf(a4[1]*TEMP_INV) : 0.f;
                v1.x = (c0   < len) ? tanhf(a4[2]*TEMP_INV) : 0.f;
                v1.y = (c0+1 < len) ? tanhf(a4[3]*TEMP_INV) : 0.f;
                *(float2*)(C + (size_t)r0*ldc + c0) = v0;
                *(float2*)(C + (size_t)r1*ldc + c0) = v1;
            }
        }
    }
}

// ---------------------------------------------------------------------------
// Stage kernels
// ---------------------------------------------------------------------------
__global__ __launch_bounds__(NT, 1)
void tc_proj_qk(const float* __restrict__ q, const float* __restrict__ k,
                const float* __restrict__ w_qs, const float* __restrict__ w_ks,
                float* __restrict__ qp, float* __restrict__ kp)
{
    const int m0 = blockIdx.y * 128, n0 = blockIdx.x * 128;
    if (blockIdx.z == 0)
        tc_body<0>(q, w_qs, DD, DD, nullptr, nullptr, 0, 0, qp, nullptr, DD, 0, m0, n0);
    else
        tc_body<0>(k, w_ks, DD, DD, nullptr, nullptr, 0, 0, kp, nullptr, DD, 0, m0, n0);
}

// Transposed projections: C_b = W (256xK) . X_b^T -> [256,1024] = [d][t]
__global__ __launch_bounds__(NT, 1)
void tc_projT(const float* __restrict__ q, const float* __restrict__ k,
              const float* __restrict__ v,
              const float* __restrict__ w_qs2, const float* __restrict__ w_ks2,
              const float* __restrict__ w_vs,
              float* __restrict__ q2t, float* __restrict__ k2t,
              float* __restrict__ vpt)
{
    const int b = blockIdx.z / 3, w = blockIdx.z % 3;
    const int m0 = blockIdx.y * 128, n0 = blockIdx.x * 128;
    const float* W; const float* X; float* C;
    if      (w == 0) { W = w_qs2; X = q; C = q2t; }
    else if (w == 1) { W = w_ks2; X = k; C = k2t; }
    else             { W = w_vs;  X = v; C = vpt; }
    tc_body<0>(W, X + (size_t)b*LL*DD, DD, DD, nullptr, nullptr, 0, 0,
               C + (size_t)b*DD*LL, nullptr, LL, 0, m0, n0);
}

// Per-batch: q2f_b = fa_b @ q2_b, k2f_b = fa_b @ k2_b. grid (2, 8, 2) z=sel
__global__ __launch_bounds__(NT, 1)
void tc_dual_b(const float* __restrict__ fa, const float* __restrict__ q2t,
               const float* __restrict__ k2t, const int* __restrict__ lens,
               float* __restrict__ q2f, float* __restrict__ k2f, int b)
{
    const int sel = blockIdx.z;
    const int m0 = blockIdx.y * 128, n0 = blockIdx.x * 128;
    const int kmax = ((lens[b] + SLAB - 1) / SLAB) * SLAB;
    const float* A = fa + (size_t)b * LL * LL;
    const float* B = (sel ? k2t : q2t) + (size_t)b * DD * LL;
    float* C = (sel ? k2f : q2f) + (size_t)b * LL * DD;
    tc_body<0>(A, B, kmax, LL, nullptr, nullptr, 0, 0, C, nullptr, DD, 0, m0, n0);
}

// Per-batch logits. grid (8, 8)
__global__ __launch_bounds__(NT, 1)
void tc_logits_b(const float* __restrict__ qp, const float* __restrict__ kp,
                 const float* __restrict__ q2f, const float* __restrict__ k2f,
                 const int* __restrict__ lens, float* __restrict__ attn, int b)
{
    const size_t od = (size_t)b * LL * DD;
    const int m0 = blockIdx.y * 128, n0 = blockIdx.x * 128;
    const int len = lens[b];
    float* out = attn + (size_t)b * LL * LL;
    if (n0 >= len) {
        const float4 z4 = make_float4(0.f, 0.f, 0.f, 0.f);
        for (int i = threadIdx.x; i < 128 * 32; i += NT) {
            int r = i >> 5, c4 = i & 31;
            *(float4*)(out + (size_t)(m0 + r) * LL + n0 + (c4 << 2)) = z4;
        }
        return;
    }
    tc_body<2>(qp + od, kp + od, DD, DD, q2f + od, k2f + od, DD, DD,
               out, nullptr, LL, len, m0, n0);
}

// Per-batch av: ov_b = attn_b @ vp_b. grid (2, 8)
__global__ __launch_bounds__(NT, 1)
void tc_av_b(const float* __restrict__ attn, const float* __restrict__ vpt,
             const int* __restrict__ lens, float* __restrict__ ov, int b)
{
    const int m0 = blockIdx.y * 128, n0 = blockIdx.x * 128;
    const int kmax = ((lens[b] + SLAB - 1) / SLAB) * SLAB;
    tc_body<0>(attn + (size_t)b * LL * LL, vpt + (size_t)b * DD * LL, kmax, LL,
               nullptr, nullptr, 0, 0, ov + (size_t)b * LL * DD, nullptr, DD, 0, m0, n0);
}

__global__ __launch_bounds__(NT, 1)
void tc_fc(const float* __restrict__ ov, const float* __restrict__ w_fc,
           const float* __restrict__ q, float* __restrict__ out)
{
    const int m0 = blockIdx.y * 128, n0 = blockIdx.x * 128;
    tc_body<1>(ov, w_fc, DD, DD, nullptr, nullptr, 0, 0, out, q, DD, 0, m0, n0);
}

// ---------------------------------------------------------------------------
// fa kernel: 8 rows per block (1024 blocks), x[b] cached in smem, warp-per-row.
// ---------------------------------------------------------------------------
__global__ __launch_bounds__(256)
void fa_kernel(const float* __restrict__ x, const float* __restrict__ fi,
               const int* __restrict__ lens, float* __restrict__ fa)
{
    __shared__ float xs[LL*FF];
    __shared__ float fis[FF];
    const int blk = blockIdx.x;
    const int b = blk >> 7, rb = blk & 127;
    const int tid = threadIdx.x;
    const float* xb = x + (size_t)b * LL * FF;
    for (int i = tid; i < LL*FF; i += 256) xs[i] = xb[i];
    if (tid < FF) fis[tid] = fi[tid];
    __syncthreads();
    const int len = lens[b];
    const int lane = tid & 31, warp = tid >> 5;

    const int i = rb*8 + warp;
    float xi[FF];
    #pragma unroll
    for (int f = 0; f < FF; f++) xi[f] = xs[i*FF + f];
    float vals[32];
    float m = -INFINITY;
    #pragma unroll
    for (int it = 0; it < 32; it++) {
        const int j = lane + it*32;
        float s = 0.f;
        #pragma unroll
        for (int f = 0; f < FF; f++) s += fabsf(xi[f] - xs[j*FF + f]) * fis[f];
        s = (j < len) ? s : -INFINITY;
        vals[it] = s;
        m = fmaxf(m, s);
    }
    #pragma unroll
    for (int o = 16; o; o >>= 1) m = fmaxf(m, __shfl_xor_sync(~0u, m, o));
    float sum = 0.f;
    #pragma unroll
    for (int it = 0; it < 32; it++) {
        float e = expf(vals[it] - m);
        vals[it] = e;
        sum += e;
    }
    #pragma unroll
    for (int o = 16; o; o >>= 1) sum += __shfl_xor_sync(~0u, sum, o);
    const float inv = 1.f / sum;
    float* outp = fa + ((size_t)b*LL + i) * LL;
    #pragma unroll
    for (int it = 0; it < 32; it++)
        outp[lane + it*32] = vals[it] * inv;
}

// ---------------------------------------------------------------------------
// LayerNorm: warp per row, 8 warps/block, shfl reductions only.
// ---------------------------------------------------------------------------
__global__ __launch_bounds__(256)
void ln_kernel(const float* __restrict__ in, const float* __restrict__ gamma,
               const float* __restrict__ beta, float* __restrict__ out)
{
    __shared__ float gs[DD], bs[DD];
    const int tid = threadIdx.x;
    if (tid < DD) { gs[tid] = gamma[tid]; bs[tid] = beta[tid]; }
    __syncthreads();

    const int lane = tid & 31, warp = tid >> 5;
    const int row = blockIdx.x * 8 + warp;
    const float* rp = in + (size_t)row * DD + lane * 8;

    float4 a0 = *(const float4*)(rp);
    float4 a1 = *(const float4*)(rp + 4);
    float v[8] = {a0.x, a0.y, a0.z, a0.w, a1.x, a1.y, a1.z, a1.w};

    float sum = 0.f;
    #pragma unroll
    for (int i = 0; i < 8; i++) sum += v[i];
    #pragma unroll
    for (int o = 16; o; o >>= 1) sum += __shfl_xor_sync(~0u, sum, o);
    const float mean = sum * (1.0f/DD);

    float vs = 0.f;
    #pragma unroll
    for (int i = 0; i < 8; i++) { v[i] -= mean; vs += v[i] * v[i]; }
    #pragma unroll
    for (int o = 16; o; o >>= 1) vs += __shfl_xor_sync(~0u, vs, o);
    const float rstd = rsqrtf(vs * (1.0f/DD) + LN_EPS);

    float* op = out + (size_t)row * DD + lane * 8;
    const int c = lane * 8;
    float4 o0, o1;
    o0.x = v[0]*rstd*gs[c+0] + bs[c+0];
    o0.y = v[1]*rstd*gs[c+1] + bs[c+1];
    o0.z = v[2]*rstd*gs[c+2] + bs[c+2];
    o0.w = v[3]*rstd*gs[c+3] + bs[c+3];
    o1.x = v[4]*rstd*gs[c+4] + bs[c+4];
    o1.y = v[5]*rstd*gs[c+5] + bs[c+5];
    o1.z = v[6]*rstd*gs[c+6] + bs[c+6];
    o1.w = v[7]*rstd*gs[c+7] + bs[c+7];
    *(float4*)(op)     = o0;
    *(float4*)(op + 4) = o1;
}

// ---------------------------------------------------------------------------
// Host launch. Per-batch pipelining over the SAME 3 extra streams that passed
// in R12 (no new streams -> no allocation-guard violation). Batch chains are
// round-robined over {default, s_fa, s_p2, s_qk}.
// ---------------------------------------------------------------------------
static cudaStream_t s_fa = nullptr, s_p2 = nullptr, s_qk = nullptr;
static cudaEvent_t  e_root = nullptr, e_fa = nullptr, e_p2 = nullptr, e_qk = nullptr;
static cudaEvent_t  e_j1 = nullptr, e_j2 = nullptr, e_j3 = nullptr;

extern "C" void kernel_launch(void* const* d_in, const int* in_sizes, int n_in,
                              void* d_out, int out_size)
{
    int li = -1;
    for (int i = 0; i < n_in; i++) if (in_sizes[i] == BB) { li = i; break; }

    const float* q = (const float*)d_in[0];
    const float* k = (const float*)d_in[1];
    const float* v = (const float*)d_in[2];
    const float* x = (const float*)d_in[3];
    const int* lens;
    const float *w_qs, *w_ks, *w_vs, *w_qs2, *w_ks2, *w_fc, *fi, *gamma, *beta;
    if (li == 4) {
        lens  = (const int*)d_in[4];
        w_qs  = (const float*)d_in[5];  w_ks  = (const float*)d_in[6];
        w_vs  = (const float*)d_in[7];  w_qs2 = (const float*)d_in[8];
        w_ks2 = (const float*)d_in[9];  w_fc  = (const float*)d_in[10];
        fi    = (const float*)d_in[11]; gamma = (const float*)d_in[12];
        beta  = (const float*)d_in[13];
    } else {
        w_qs  = (const float*)d_in[4];  w_ks  = (const float*)d_in[5];
        w_vs  = (const float*)d_in[6];  w_qs2 = (const float*)d_in[7];
        w_ks2 = (const float*)d_in[8];  w_fc  = (const float*)d_in[9];
        fi    = (const float*)d_in[10]; gamma = (const float*)d_in[11];
        beta  = (const float*)d_in[12]; lens  = (const int*)d_in[13];
    }

    float *qp, *kp, *q2t, *k2t, *vpt, *q2f, *k2f, *ov, *fc, *fa, *attn_scratch;
    cudaGetSymbolAddress((void**)&qp,  g_qp);
    cudaGetSymbolAddress((void**)&kp,  g_kp);
    cudaGetSymbolAddress((void**)&q2t, g_q2t);
    cudaGetSymbolAddress((void**)&k2t, g_k2t);
    cudaGetSymbolAddress((void**)&vpt, g_vpt);
    cudaGetSymbolAddress((void**)&q2f, g_q2f);
    cudaGetSymbolAddress((void**)&k2f, g_k2f);
    cudaGetSymbolAddress((void**)&ov,  g_ov);
    cudaGetSymbolAddress((void**)&fc,  g_fc);
    cudaGetSymbolAddress((void**)&fa,  g_fa);
    cudaGetSymbolAddress((void**)&attn_scratch, g_attn_scratch);

    const size_t OUT_ELEMS  = (size_t)BB*LL*DD;
    const size_t ATTN_ELEMS = (size_t)BB*LL*LL;
    float* attn = ((size_t)out_size >= OUT_ELEMS + ATTN_ELEMS)
                ? (float*)d_out + OUT_ELEMS
                : attn_scratch;

    if (!s_fa) {
        cudaStreamCreateWithFlags(&s_fa, cudaStreamNonBlocking);
        cudaStreamCreateWithFlags(&s_p2, cudaStreamNonBlocking);
        cudaStreamCreateWithFlags(&s_qk, cudaStreamNonBlocking);
        cudaEventCreateWithFlags(&e_root, cudaEventDisableTiming);
        cudaEventCreateWithFlags(&e_fa,   cudaEventDisableTiming);
        cudaEventCreateWithFlags(&e_p2,   cudaEventDisableTiming);
        cudaEventCreateWithFlags(&e_qk,   cudaEventDisableTiming);
        cudaEventCreateWithFlags(&e_j1,   cudaEventDisableTiming);
        cudaEventCreateWithFlags(&e_j2,   cudaEventDisableTiming);
        cudaEventCreateWithFlags(&e_j3,   cudaEventDisableTiming);
        cudaFuncSetAttribute(tc_proj_qk, cudaFuncAttributeMaxDynamicSharedMemorySize, SMEM_DYN);
        cudaFuncSetAttribute(tc_projT,   cudaFuncAttributeMaxDynamicSharedMemorySize, SMEM_DYN);
        cudaFuncSetAttribute(tc_dual_b,  cudaFuncAttributeMaxDynamicSharedMemorySize, SMEM_DYN);
        cudaFuncSetAttribute(tc_logits_b,cudaFuncAttributeMaxDynamicSharedMemorySize, SMEM_DYN);
        cudaFuncSetAttribute(tc_av_b,    cudaFuncAttributeMaxDynamicSharedMemorySize, SMEM_DYN);
        cudaFuncSetAttribute(tc_fc,      cudaFuncAttributeMaxDynamicSharedMemorySize, SMEM_DYN);
    }

    const int M = BB * LL;  // 8192
    dim3 blk(NT);
    dim3 blk256(256);

    // ---- Front section: fa, projT, proj_qk concurrent ----
    cudaEventRecord(e_root, 0);
    cudaStreamWaitEvent(s_fa, e_root, 0);
    cudaStreamWaitEvent(s_p2, e_root, 0);
    cudaStreamWaitEvent(s_qk, e_root, 0);

    fa_kernel<<<BB*128, blk256, 0, s_fa>>>(x, fi, lens, fa);
    cudaEventRecord(e_fa, s_fa);

    tc_projT<<<dim3(LL/128, DD/128, 3*BB), blk, SMEM_DYN, s_p2>>>(
        q, k, v, w_qs2, w_ks2, w_vs, q2t, k2t, vpt);
    cudaEventRecord(e_p2, s_p2);

    tc_proj_qk<<<dim3(DD/128, M/128, 2), blk, SMEM_DYN, s_qk>>>(q, k, w_qs, w_ks, qp, kp);
    cudaEventRecord(e_qk, s_qk);

    // ---- Per-batch pipelined chains over 4 streams (2 chains each) ----
    cudaStream_t chains[4] = { (cudaStream_t)0, s_fa, s_p2, s_qk };
    // Each chain stream must see fa + projT done before its first dual,
    // and proj_qk done before its first logits.
    for (int c = 0; c < 4; c++) {
        cudaStreamWaitEvent(chains[c], e_fa, 0);
        cudaStreamWaitEvent(chains[c], e_p2, 0);
    }
    for (int b = 0; b < BB; b++) {
        cudaStream_t st = chains[b & 3];
        tc_dual_b<<<dim3(DD/128, LL/128, 2), blk, SMEM_DYN, st>>>(
            fa, q2t, k2t, lens, q2f, k2f, b);
        if (b < 4) cudaStreamWaitEvent(st, e_qk, 0);   // once per stream
        tc_logits_b<<<dim3(LL/128, LL/128), blk, SMEM_DYN, st>>>(
            qp, kp, q2f, k2f, lens, attn, b);
        tc_av_b<<<dim3(DD/128, LL/128), blk, SMEM_DYN, st>>>(
            attn, vpt, lens, ov, b);
    }
    cudaEventRecord(e_j1, s_fa);
    cudaEventRecord(e_j2, s_p2);
    cudaEventRecord(e_j3, s_qk);

    // ---- Tail: fc + residual, layernorm (default stream joins all) ----
    cudaStreamWaitEvent(0, e_j1, 0);
    cudaStreamWaitEvent(0, e_j2, 0);
    cudaStreamWaitEvent(0, e_j3, 0);
    tc_fc<<<dim3(DD/128, M/128, 1), blk, SMEM_DYN>>>(ov, w_fc, q, fc);
    ln_kernel<<<M/8, blk256>>>(fc, gamma, beta, (float*)d_out);
}

// round 15
// speedup vs baseline: 1.2057x; 1.2057x over previous
#include <cuda_runtime.h>
#include <cuda_fp16.h>
#include <math.h>
#include <stdint.h>

// Problem constants
#define BB 8
#define LL 1024
#define DD 256
#define FF 11
#define TEMP_INV (1.0f/16.0f)
#define LN_EPS 1e-6f

// GEMM config: 128x128 CTA tile, K-slab 64, 16 warps (4m x 4n), warp tile 32x32
// fp16 2-pass: D = aH*bH + aH*bL  (dropped aL*b ~ 2^-11)
#define SLAB 64
#define TB 16384                // one 128x64 fp16 tile (128 rows x 128B)
#define BUFB (3*TB)             // AH BH BL = 48KB
#define SMEM_DYN (2*BUFB)       // 98304 (double buffered)
#define NT 512                  // threads per CTA

// ---------------------------------------------------------------------------
// Scratch
// ---------------------------------------------------------------------------
__device__ float g_qp [BB*LL*DD];
__device__ float g_kp [BB*LL*DD];
__device__ float g_vp [BB*LL*DD];   // [b][t][d]
__device__ float g_q2t[BB*LL*DD];   // [b][d][t]
__device__ float g_k2t[BB*LL*DD];
__device__ float g_vwt[BB*LL*DD];   // [b][d][t]  (vw = vp @ w_fc^T, transposed)
__device__ float g_q2f[BB*LL*DD];
__device__ float g_k2f[BB*LL*DD];
__device__ float g_fc [BB*LL*DD];
__device__ float g_fa [(size_t)BB*LL*LL];
__device__ float g_attn_scratch[(size_t)BB*LL*LL];

// ---------------------------------------------------------------------------
// Helpers
// ---------------------------------------------------------------------------
__device__ __forceinline__ uint32_t smem_u32(const void* p) {
    uint32_t a;
    asm("{ .reg .u64 t; cvta.to.shared.u64 t, %1; cvt.u32.u64 %0, t; }"
        : "=r"(a) : "l"(p));
    return a;
}

__device__ __forceinline__ void ldsm_x4(uint32_t* r, uint32_t a) {
    asm volatile("ldmatrix.sync.aligned.m8n8.x4.shared.b16 {%0,%1,%2,%3}, [%4];"
        : "=r"(r[0]), "=r"(r[1]), "=r"(r[2]), "=r"(r[3]) : "r"(a));
}

__device__ __forceinline__ void mma16816(float* c, const uint32_t* a, const uint32_t* b) {
    asm volatile("mma.sync.aligned.m16n8k16.row.col.f32.f16.f16.f32 "
        "{%0,%1,%2,%3}, {%4,%5,%6,%7}, {%8,%9}, {%0,%1,%2,%3};"
        : "+f"(c[0]), "+f"(c[1]), "+f"(c[2]), "+f"(c[3])
        : "r"(a[0]), "r"(a[1]), "r"(a[2]), "r"(a[3]), "r"(b[0]), "r"(b[1]));
}

__device__ __forceinline__ uint32_t pack_h2(float x, float y) {
    __half2 h = __floats2half2_rn(x, y);
    return *(uint32_t*)&h;
}

// Load a 128x64 fp32 tile into registers (4 float4 per thread, 512 threads).
__device__ __forceinline__
void ld_tile(const float* __restrict__ src, int r0, int ld, int k0,
             float4* v, int tid)
{
    #pragma unroll
    for (int i = 0; i < 4; i++) {
        int f = tid + (i << 9);
        int row = f >> 4, c4 = f & 15;
        v[i] = *(const float4*)(src + (size_t)(r0 + row) * ld + k0 + (c4 << 2));
    }
}

// A tile: fp16 hi only, SW128-swizzled.
__device__ __forceinline__
void st_tile_a(const float4* v, char* smem, uint32_t off, int tid)
{
    #pragma unroll
    for (int i = 0; i < 4; i++) {
        int f = tid + (i << 9);
        int row = f >> 4, c4 = f & 15;
        float4 a = v[i];
        uint32_t byte = (row << 7) + (c4 << 3);
        uint32_t sw = byte ^ ((byte >> 3) & 0x70);
        *(uint2*)(smem + off + sw) = make_uint2(pack_h2(a.x, a.y), pack_h2(a.z, a.w));
    }
}

// B tile: fp16 hi + lo (residual), SW128-swizzled.
__device__ __forceinline__
void st_tile_b(const float4* v, char* smem, uint32_t hiOff, uint32_t loOff, int tid)
{
    #pragma unroll
    for (int i = 0; i < 4; i++) {
        int f = tid + (i << 9);
        int row = f >> 4, c4 = f & 15;
        float4 a = v[i];
        __half2 h01 = __floats2half2_rn(a.x, a.y);
        __half2 h23 = __floats2half2_rn(a.z, a.w);
        float rx = a.x - __low2float(h01);
        float ry = a.y - __high2float(h01);
        float rz = a.z - __low2float(h23);
        float rw = a.w - __high2float(h23);
        uint32_t byte = (row << 7) + (c4 << 3);
        uint32_t sw = byte ^ ((byte >> 3) & 0x70);
        *(uint2*)(smem + hiOff + sw) = make_uint2(*(uint32_t*)&h01, *(uint32_t*)&h23);
        *(uint2*)(smem + loOff + sw) = make_uint2(pack_h2(rx, ry), pack_h2(rz, rw));
    }
}

// ---------------------------------------------------------------------------
// fp16x2 mma.sync GEMM body. NT: C[m,n] = sum_k A[m,k]*B[n,k] over
// (A1,B1,kext1,ld1) then (A2,B2,kext2,ld2). kext may be < ld (masked K).
// MODE: 0 plain, 1 +add residual, 2 tanh(acc/16) w/ col mask
// ---------------------------------------------------------------------------
template<int MODE>
__device__ __forceinline__
void tc_body(const float* __restrict__ A1, const float* __restrict__ B1,
             int k1, int ld1,
             const float* __restrict__ A2, const float* __restrict__ B2,
             int k2, int ld2,
             float* __restrict__ C, const float* __restrict__ add,
             int ldc, int len, int m0, int n0)
{
    extern __shared__ char smem[];
    const uint32_t sb = smem_u32(smem);
    const int tid = threadIdx.x;
    const int lane = tid & 31, wid = tid >> 5;
    const int wm = wid & 3, wn = wid >> 2;

    float acc[2][4][4] = {};

    // ldmatrix lane addressing (128B rows, SW128-style XOR)
    const int a_row = wm * 32 + (lane & 15);
    const uint32_t a_colp = (lane >> 4) << 4;
    const uint32_t a_xor = (uint32_t)(a_row & 7) << 4;
    const int b_row = wn * 32 + ((lane >> 4) << 3) + (lane & 7);
    const uint32_t b_colp = ((lane >> 3) & 1) << 4;
    const uint32_t b_xor = (uint32_t)(b_row & 7) << 4;

    const int n1 = k1 / SLAB;
    const int nslabs = n1 + (A2 ? k2 / SLAB : 0);

    float4 av[4], bv[4];
    // prologue: slab 0
    ld_tile(A1, m0, ld1, 0, av, tid);
    ld_tile(B1, n0, ld1, 0, bv, tid);
    st_tile_a(av, smem, 0, tid);
    st_tile_b(bv, smem, TB, 2*TB, tid);
    __syncthreads();

    for (int s = 0; s < nslabs; s++) {
        const uint32_t bo = (s & 1) * BUFB;
        const uint32_t bn = bo ^ BUFB;
        const bool has = (s + 1) < nslabs;
        const float *An = A1, *Bn = B1; int ldn = ld1, k0n = 0;
        if (has) {
            int sn = s + 1;
            if (sn < n1) { An = A1; Bn = B1; ldn = ld1; k0n = sn * SLAB; }
            else         { An = A2; Bn = B2; ldn = ld2; k0n = (sn - n1) * SLAB; }
        }

        #pragma unroll
        for (int kk = 0; kk < 4; kk++) {
            if (kk == 0 && has) ld_tile(An, m0, ldn, k0n, av, tid);
            if (kk == 2 && has) {
                st_tile_a(av, smem, bn, tid);
                ld_tile(Bn, n0, ldn, k0n, bv, tid);
            }
            if (kk == 3 && has) st_tile_b(bv, smem, bn + TB, bn + 2*TB, tid);

            const uint32_t kb = kk << 5;
            uint32_t bH[8], bL[8];
            {
                uint32_t r = (uint32_t)b_row << 7;
                uint32_t c = (kb + b_colp) ^ b_xor;
                ldsm_x4(bH + 0, sb + bo + TB + r + c);
                ldsm_x4(bH + 4, sb + bo + TB + r + 2048 + c);
                ldsm_x4(bL + 0, sb + bo + 2*TB + r + c);
                ldsm_x4(bL + 4, sb + bo + 2*TB + r + 2048 + c);
            }
            #pragma unroll
            for (int mt = 0; mt < 2; mt++) {
                uint32_t aH[4];
                uint32_t r = (uint32_t)(a_row + mt*16) << 7;
                uint32_t c = (kb + a_colp) ^ a_xor;
                ldsm_x4(aH, sb + bo + r + c);
                #pragma unroll
                for (int nt = 0; nt < 4; nt++) {
                    mma16816(acc[mt][nt], aH, bH + nt*2);
                    mma16816(acc[mt][nt], aH, bL + nt*2);
                }
            }
        }
        if (has) __syncthreads();
    }

    // epilogue
    const int mg = m0 + wm * 32;
    const int ng = n0 + wn * 32;
    const int rq = lane >> 2;
    const int cq = (lane & 3) << 1;
    #pragma unroll
    for (int mt = 0; mt < 2; mt++) {
        #pragma unroll
        for (int nt = 0; nt < 4; nt++) {
            const float* a4 = acc[mt][nt];
            const int r0 = mg + mt*16 + rq, r1 = r0 + 8;
            const int c0 = ng + nt*8 + cq;
            if (MODE == 0) {
                *(float2*)(C + (size_t)r0*ldc + c0) = make_float2(a4[0], a4[1]);
                *(float2*)(C + (size_t)r1*ldc + c0) = make_float2(a4[2], a4[3]);
            } else if (MODE == 1) {
                float2 x0 = *(const float2*)(add + (size_t)r0*ldc + c0);
                float2 x1 = *(const float2*)(add + (size_t)r1*ldc + c0);
                *(float2*)(C + (size_t)r0*ldc + c0) = make_float2(a4[0]+x0.x, a4[1]+x0.y);
                *(float2*)(C + (size_t)r1*ldc + c0) = make_float2(a4[2]+x1.x, a4[3]+x1.y);
            } else {
                float2 v0, v1;
                v0.x = (c0   < len) ? tanhf(a4[0]*TEMP_INV) : 0.f;
                v0.y = (c0+1 < len) ? tanhf(a4[1]*TEMP_INV) : 0.f;
                v1.x = (c0   < len) ? tanhf(a4[2]*TEMP_INV) : 0.f;
                v1.y = (c0+1 < len) ? tanhf(a4[3]*TEMP_INV) : 0.f;
                *(float2*)(C + (size_t)r0*ldc + c0) = v0;
                *(float2*)(C + (size_t)r1*ldc + c0) = v1;
            }
        }
    }
}

// ---------------------------------------------------------------------------
// Stage kernels
// ---------------------------------------------------------------------------
// q/k/v projections: [8192,256] x [256,256], z selects which.
__global__ __launch_bounds__(NT, 1)
void tc_proj_qkv(const float* __restrict__ q, const float* __restrict__ k,
                 const float* __restrict__ v,
                 const float* __restrict__ w_qs, const float* __restrict__ w_ks,
                 const float* __restrict__ w_vs,
                 float* __restrict__ qp, float* __restrict__ kp,
                 float* __restrict__ vp)
{
    const int m0 = blockIdx.y * 128, n0 = blockIdx.x * 128;
    const float* A; const float* W; float* C;
    if      (blockIdx.z == 0) { A = q; W = w_qs; C = qp; }
    else if (blockIdx.z == 1) { A = k; W = w_ks; C = kp; }
    else                      { A = v; W = w_vs; C = vp; }
    tc_body<0>(A, W, DD, DD, nullptr, nullptr, 0, 0, C, nullptr, DD, 0, m0, n0);
}

// Transposed projections: C_b = W (256x256) . X_b^T -> [256,1024] = [d][t]
// z = b*2 + w  (w: 0=qs2, 1=ks2)
__global__ __launch_bounds__(NT, 1)
void tc_projT(const float* __restrict__ q, const float* __restrict__ k,
              const float* __restrict__ w_qs2, const float* __restrict__ w_ks2,
              float* __restrict__ q2t, float* __restrict__ k2t)
{
    const int b = blockIdx.z >> 1, w = blockIdx.z & 1;
    const int m0 = blockIdx.y * 128, n0 = blockIdx.x * 128;
    const float* W = w ? w_ks2 : w_qs2;
    const float* X = (w ? k : q) + (size_t)b*LL*DD;
    float* C = (w ? k2t : q2t) + (size_t)b*DD*LL;
    tc_body<0>(W, X, DD, DD, nullptr, nullptr, 0, 0, C, nullptr, LL, 0, m0, n0);
}

// vwt_b = w_fc @ vp_b^T -> [256,1024]. grid (LL/128, DD/128, BB)
__global__ __launch_bounds__(NT, 1)
void tc_vw(const float* __restrict__ vp, const float* __restrict__ w_fc,
           float* __restrict__ vwt)
{
    const int b = blockIdx.z;
    const int m0 = blockIdx.y * 128, n0 = blockIdx.x * 128;
    tc_body<0>(w_fc, vp + (size_t)b*LL*DD, DD, DD, nullptr, nullptr, 0, 0,
               vwt + (size_t)b*DD*LL, nullptr, LL, 0, m0, n0);
}

// q2f = fa @ q2 (NT with q2t), k2f = fa @ k2. K masked to ceil(len/64)*64.
__global__ __launch_bounds__(NT, 1)
void tc_dual(const float* __restrict__ fa, const float* __restrict__ q2t,
             const float* __restrict__ k2t, const int* __restrict__ lens,
             float* __restrict__ q2f, float* __restrict__ k2f)
{
    const int b = blockIdx.z >> 1, sel = blockIdx.z & 1;
    const int m0 = blockIdx.y * 128, n0 = blockIdx.x * 128;
    const int kmax = ((lens[b] + SLAB - 1) / SLAB) * SLAB;   // fa cols >= len are 0
    const float* A = fa + (size_t)b * LL * LL;
    const float* B = (sel ? k2t : q2t) + (size_t)b * DD * LL;
    float* C = (sel ? k2f : q2f) + (size_t)b * LL * DD;
    tc_body<0>(A, B, kmax, LL, nullptr, nullptr, 0, 0, C, nullptr, DD, 0, m0, n0);
}

__global__ __launch_bounds__(NT, 1)
void tc_logits(const float* __restrict__ qp, const float* __restrict__ kp,
               const float* __restrict__ q2f, const float* __restrict__ k2f,
               const int* __restrict__ lens, float* __restrict__ attn)
{
    const int b = blockIdx.z;
    const size_t od = (size_t)b * LL * DD;
    const int m0 = blockIdx.y * 128, n0 = blockIdx.x * 128;
    const int len = lens[b];
    float* out = attn + (size_t)b * LL * LL;
    if (n0 >= len) {
        const float4 z4 = make_float4(0.f, 0.f, 0.f, 0.f);
        for (int i = threadIdx.x; i < 128 * 32; i += NT) {
            int r = i >> 5, c4 = i & 31;
            *(float4*)(out + (size_t)(m0 + r) * LL + n0 + (c4 << 2)) = z4;
        }
        return;
    }
    tc_body<2>(qp + od, kp + od, DD, DD, q2f + od, k2f + od, DD, DD,
               out, nullptr, LL, len, m0, n0);
}

// out_pre = attn @ vw + q  (vw pre-multiplied by w_fc; residual fused).
__global__ __launch_bounds__(NT, 1)
void tc_av(const float* __restrict__ attn, const float* __restrict__ vwt,
           const int* __restrict__ lens, const float* __restrict__ q,
           float* __restrict__ fc)
{
    const int b = blockIdx.z;
    const int m0 = blockIdx.y * 128, n0 = blockIdx.x * 128;
    const int kmax = ((lens[b] + SLAB - 1) / SLAB) * SLAB;
    tc_body<1>(attn + (size_t)b * LL * LL, vwt + (size_t)b * DD * LL, kmax, LL,
               nullptr, nullptr, 0, 0,
               fc + (size_t)b * LL * DD, q + (size_t)b * LL * DD, DD, 0, m0, n0);
}

// ---------------------------------------------------------------------------
// fa kernel: 8 rows per block (1024 blocks), x[b] cached in smem, warp-per-row.
// ---------------------------------------------------------------------------
__global__ __launch_bounds__(256)
void fa_kernel(const float* __restrict__ x, const float* __restrict__ fi,
               const int* __restrict__ lens, float* __restrict__ fa)
{
    __shared__ float xs[LL*FF];
    __shared__ float fis[FF];
    const int blk = blockIdx.x;
    const int b = blk >> 7, rb = blk & 127;
    const int tid = threadIdx.x;
    const float* xb = x + (size_t)b * LL * FF;
    for (int i = tid; i < LL*FF; i += 256) xs[i] = xb[i];
    if (tid < FF) fis[tid] = fi[tid];
    __syncthreads();
    const int len = lens[b];
    const int lane = tid & 31, warp = tid >> 5;

    const int i = rb*8 + warp;
    float xi[FF];
    #pragma unroll
    for (int f = 0; f < FF; f++) xi[f] = xs[i*FF + f];
    float vals[32];
    float m = -INFINITY;
    #pragma unroll
    for (int it = 0; it < 32; it++) {
        const int j = lane + it*32;
        float s = 0.f;
        #pragma unroll
        for (int f = 0; f < FF; f++) s += fabsf(xi[f] - xs[j*FF + f]) * fis[f];
        s = (j < len) ? s : -INFINITY;
        vals[it] = s;
        m = fmaxf(m, s);
    }
    #pragma unroll
    for (int o = 16; o; o >>= 1) m = fmaxf(m, __shfl_xor_sync(~0u, m, o));
    float sum = 0.f;
    #pragma unroll
    for (int it = 0; it < 32; it++) {
        float e = expf(vals[it] - m);
        vals[it] = e;
        sum += e;
    }
    #pragma unroll
    for (int o = 16; o; o >>= 1) sum += __shfl_xor_sync(~0u, sum, o);
    const float inv = 1.f / sum;
    float* outp = fa + ((size_t)b*LL + i) * LL;
    #pragma unroll
    for (int it = 0; it < 32; it++)
        outp[lane + it*32] = vals[it] * inv;
}

// ---------------------------------------------------------------------------
// LayerNorm: warp per row, 8 warps/block, shfl reductions only.
// ---------------------------------------------------------------------------
__global__ __launch_bounds__(256)
void ln_kernel(const float* __restrict__ in, const float* __restrict__ gamma,
               const float* __restrict__ beta, float* __restrict__ out)
{
    __shared__ float gs[DD], bs[DD];
    const int tid = threadIdx.x;
    if (tid < DD) { gs[tid] = gamma[tid]; bs[tid] = beta[tid]; }
    __syncthreads();

    const int lane = tid & 31, warp = tid >> 5;
    const int row = blockIdx.x * 8 + warp;
    const float* rp = in + (size_t)row * DD + lane * 8;

    float4 a0 = *(const float4*)(rp);
    float4 a1 = *(const float4*)(rp + 4);
    float v[8] = {a0.x, a0.y, a0.z, a0.w, a1.x, a1.y, a1.z, a1.w};

    float sum = 0.f;
    #pragma unroll
    for (int i = 0; i < 8; i++) sum += v[i];
    #pragma unroll
    for (int o = 16; o; o >>= 1) sum += __shfl_xor_sync(~0u, sum, o);
    const float mean = sum * (1.0f/DD);

    float vs = 0.f;
    #pragma unroll
    for (int i = 0; i < 8; i++) { v[i] -= mean; vs += v[i] * v[i]; }
    #pragma unroll
    for (int o = 16; o; o >>= 1) vs += __shfl_xor_sync(~0u, vs, o);
    const float rstd = rsqrtf(vs * (1.0f/DD) + LN_EPS);

    float* op = out + (size_t)row * DD + lane * 8;
    const int c = lane * 8;
    float4 o0, o1;
    o0.x = v[0]*rstd*gs[c+0] + bs[c+0];
    o0.y = v[1]*rstd*gs[c+1] + bs[c+1];
    o0.z = v[2]*rstd*gs[c+2] + bs[c+2];
    o0.w = v[3]*rstd*gs[c+3] + bs[c+3];
    o1.x = v[4]*rstd*gs[c+4] + bs[c+4];
    o1.y = v[5]*rstd*gs[c+5] + bs[c+5];
    o1.z = v[6]*rstd*gs[c+6] + bs[c+6];
    o1.w = v[7]*rstd*gs[c+7] + bs[c+7];
    *(float4*)(op)     = o0;
    *(float4*)(op + 4) = o1;
}

// ---------------------------------------------------------------------------
// Host launch (R12's proven 3-extra-stream DAG; fc stage eliminated by
// associativity: out = attn @ (vp @ w_fc^T) + q)
// ---------------------------------------------------------------------------
static cudaStream_t s_fa = nullptr, s_p2 = nullptr, s_qk = nullptr;
static cudaEvent_t  e_root = nullptr, e_fa = nullptr, e_p2 = nullptr,
                    e_qk = nullptr, e_vw = nullptr;

extern "C" void kernel_launch(void* const* d_in, const int* in_sizes, int n_in,
                              void* d_out, int out_size)
{
    int li = -1;
    for (int i = 0; i < n_in; i++) if (in_sizes[i] == BB) { li = i; break; }

    const float* q = (const float*)d_in[0];
    const float* k = (const float*)d_in[1];
    const float* v = (const float*)d_in[2];
    const float* x = (const float*)d_in[3];
    const int* lens;
    const float *w_qs, *w_ks, *w_vs, *w_qs2, *w_ks2, *w_fc, *fi, *gamma, *beta;
    if (li == 4) {
        lens  = (const int*)d_in[4];
        w_qs  = (const float*)d_in[5];  w_ks  = (const float*)d_in[6];
        w_vs  = (const float*)d_in[7];  w_qs2 = (const float*)d_in[8];
        w_ks2 = (const float*)d_in[9];  w_fc  = (const float*)d_in[10];
        fi    = (const float*)d_in[11]; gamma = (const float*)d_in[12];
        beta  = (const float*)d_in[13];
    } else {
        w_qs  = (const float*)d_in[4];  w_ks  = (const float*)d_in[5];
        w_vs  = (const float*)d_in[6];  w_qs2 = (const float*)d_in[7];
        w_ks2 = (const float*)d_in[8];  w_fc  = (const float*)d_in[9];
        fi    = (const float*)d_in[10]; gamma = (const float*)d_in[11];
        beta  = (const float*)d_in[12]; lens  = (const int*)d_in[13];
    }

    float *qp, *kp, *vp, *q2t, *k2t, *vwt, *q2f, *k2f, *fc, *fa, *attn_scratch;
    cudaGetSymbolAddress((void**)&qp,  g_qp);
    cudaGetSymbolAddress((void**)&kp,  g_kp);
    cudaGetSymbolAddress((void**)&vp,  g_vp);
    cudaGetSymbolAddress((void**)&q2t, g_q2t);
    cudaGetSymbolAddress((void**)&k2t, g_k2t);
    cudaGetSymbolAddress((void**)&vwt, g_vwt);
    cudaGetSymbolAddress((void**)&q2f, g_q2f);
    cudaGetSymbolAddress((void**)&k2f, g_k2f);
    cudaGetSymbolAddress((void**)&fc,  g_fc);
    cudaGetSymbolAddress((void**)&fa,  g_fa);
    cudaGetSymbolAddress((void**)&attn_scratch, g_attn_scratch);

    const size_t OUT_ELEMS  = (size_t)BB*LL*DD;
    const size_t ATTN_ELEMS = (size_t)BB*LL*LL;
    float* attn = ((size_t)out_size >= OUT_ELEMS + ATTN_ELEMS)
                ? (float*)d_out + OUT_ELEMS
                : attn_scratch;

    if (!s_fa) {
        cudaStreamCreateWithFlags(&s_fa, cudaStreamNonBlocking);
        cudaStreamCreateWithFlags(&s_p2, cudaStreamNonBlocking);
        cudaStreamCreateWithFlags(&s_qk, cudaStreamNonBlocking);
        cudaEventCreateWithFlags(&e_root, cudaEventDisableTiming);
        cudaEventCreateWithFlags(&e_fa,   cudaEventDisableTiming);
        cudaEventCreateWithFlags(&e_p2,   cudaEventDisableTiming);
        cudaEventCreateWithFlags(&e_qk,   cudaEventDisableTiming);
        cudaEventCreateWithFlags(&e_vw,   cudaEventDisableTiming);
        cudaFuncSetAttribute(tc_proj_qkv, cudaFuncAttributeMaxDynamicSharedMemorySize, SMEM_DYN);
        cudaFuncSetAttribute(tc_projT,    cudaFuncAttributeMaxDynamicSharedMemorySize, SMEM_DYN);
        cudaFuncSetAttribute(tc_vw,       cudaFuncAttributeMaxDynamicSharedMemorySize, SMEM_DYN);
        cudaFuncSetAttribute(tc_dual,     cudaFuncAttributeMaxDynamicSharedMemorySize, SMEM_DYN);
        cudaFuncSetAttribute(tc_logits,   cudaFuncAttributeMaxDynamicSharedMemorySize, SMEM_DYN);
        cudaFuncSetAttribute(tc_av,       cudaFuncAttributeMaxDynamicSharedMemorySize, SMEM_DYN);
    }

    const int M = BB * LL;  // 8192
    dim3 blk(NT);
    dim3 blk256(256);

    // ---- Front section: fa, projT, proj_qkv(+vw) concurrent ----
    cudaEventRecord(e_root, 0);
    cudaStreamWaitEvent(s_fa, e_root, 0);
    cudaStreamWaitEvent(s_p2, e_root, 0);
    cudaStreamWaitEvent(s_qk, e_root, 0);

    fa_kernel<<<BB*128, blk256, 0, s_fa>>>(x, fi, lens, fa);
    cudaEventRecord(e_fa, s_fa);

    tc_projT<<<dim3(LL/128, DD/128, 2*BB), blk, SMEM_DYN, s_p2>>>(
        q, k, w_qs2, w_ks2, q2t, k2t);
    cudaEventRecord(e_p2, s_p2);

    tc_proj_qkv<<<dim3(DD/128, M/128, 3), blk, SMEM_DYN, s_qk>>>(
        q, k, v, w_qs, w_ks, w_vs, qp, kp, vp);
    cudaEventRecord(e_qk, s_qk);
    tc_vw<<<dim3(LL/128, DD/128, BB), blk, SMEM_DYN, s_qk>>>(vp, w_fc, vwt);
    cudaEventRecord(e_vw, s_qk);

    // ---- Back chain (fused, R12-style) ----
    cudaStreamWaitEvent(0, e_fa, 0);
    cudaStreamWaitEvent(0, e_p2, 0);
    tc_dual<<<dim3(DD/128, LL/128, BB*2), blk, SMEM_DYN>>>(fa, q2t, k2t, lens, q2f, k2f);

    cudaStreamWaitEvent(0, e_qk, 0);
    tc_logits<<<dim3(LL/128, LL/128, BB), blk, SMEM_DYN>>>(qp, kp, q2f, k2f, lens, attn);

    cudaStreamWaitEvent(0, e_vw, 0);
    tc_av<<<dim3(DD/128, LL/128, BB), blk, SMEM_DYN>>>(attn, vwt, lens, q, fc);

    ln_kernel<<<M/8, blk256>>>(fc, gamma, beta, (float*)d_out);
}

// round 16
// speedup vs baseline: 1.2338x; 1.0233x over previous
#include <cuda_runtime.h>
#include <cuda_fp16.h>
#include <math.h>
#include <stdint.h>

// Problem constants
#define BB 8
#define LL 1024
#define DD 256
#define FF 11
#define TEMP_INV (1.0f/16.0f)
#define LN_EPS 1e-6f

// GEMM config: 128x128 CTA tile, K-slab 64, 16 warps (4m x 4n), warp tile 32x32
// fp16 2-pass: D = aH*bH + aH*bL  (dropped aL*b ~ 2^-11)
#define SLAB 64
#define TB 16384                // one 128x64 fp16 tile (128 rows x 128B)
#define BUFB (3*TB)             // AH BH BL = 48KB
#define SMEM_DYN (2*BUFB)       // 98304 (double buffered)
#define NT 512                  // threads per CTA

// ---------------------------------------------------------------------------
// Scratch
// ---------------------------------------------------------------------------
__device__ float g_qp [BB*LL*DD];
__device__ float g_kp [BB*LL*DD];
__device__ float g_vp [BB*LL*DD];   // [b][t][d]
__device__ float g_q2t[BB*LL*DD];   // [b][d][t]
__device__ float g_k2t[BB*LL*DD];
__device__ float g_vwt[BB*LL*DD];   // [b][d][t]  (vw = vp @ w_fc^T, transposed)
__device__ float g_q2f[BB*LL*DD];
__device__ float g_k2f[BB*LL*DD];
__device__ float g_fc [BB*LL*DD];
__device__ float g_fa [(size_t)BB*LL*LL];
__device__ float g_attn_scratch[(size_t)BB*LL*LL];

// ---------------------------------------------------------------------------
// Helpers
// ---------------------------------------------------------------------------
__device__ __forceinline__ uint32_t smem_u32(const void* p) {
    uint32_t a;
    asm("{ .reg .u64 t; cvta.to.shared.u64 t, %1; cvt.u32.u64 %0, t; }"
        : "=r"(a) : "l"(p));
    return a;
}

__device__ __forceinline__ void ldsm_x4(uint32_t* r, uint32_t a) {
    asm volatile("ldmatrix.sync.aligned.m8n8.x4.shared.b16 {%0,%1,%2,%3}, [%4];"
        : "=r"(r[0]), "=r"(r[1]), "=r"(r[2]), "=r"(r[3]) : "r"(a));
}

__device__ __forceinline__ void mma16816(float* c, const uint32_t* a, const uint32_t* b) {
    asm volatile("mma.sync.aligned.m16n8k16.row.col.f32.f16.f16.f32 "
        "{%0,%1,%2,%3}, {%4,%5,%6,%7}, {%8,%9}, {%0,%1,%2,%3};"
        : "+f"(c[0]), "+f"(c[1]), "+f"(c[2]), "+f"(c[3])
        : "r"(a[0]), "r"(a[1]), "r"(a[2]), "r"(a[3]), "r"(b[0]), "r"(b[1]));
}

__device__ __forceinline__ uint32_t pack_h2(float x, float y) {
    __half2 h = __floats2half2_rn(x, y);
    return *(uint32_t*)&h;
}

// Load a 128x64 fp32 tile into registers (4 float4 per thread, 512 threads).
__device__ __forceinline__
void ld_tile(const float* __restrict__ src, int r0, int ld, int k0,
             float4* v, int tid)
{
    #pragma unroll
    for (int i = 0; i < 4; i++) {
        int f = tid + (i << 9);
        int row = f >> 4, c4 = f & 15;
        v[i] = *(const float4*)(src + (size_t)(r0 + row) * ld + k0 + (c4 << 2));
    }
}

// A tile: fp16 hi only, SW128-swizzled.
__device__ __forceinline__
void st_tile_a(const float4* v, char* smem, uint32_t off, int tid)
{
    #pragma unroll
    for (int i = 0; i < 4; i++) {
        int f = tid + (i << 9);
        int row = f >> 4, c4 = f & 15;
        float4 a = v[i];
        uint32_t byte = (row << 7) + (c4 << 3);
        uint32_t sw = byte ^ ((byte >> 3) & 0x70);
        *(uint2*)(smem + off + sw) = make_uint2(pack_h2(a.x, a.y), pack_h2(a.z, a.w));
    }
}

// B tile: fp16 hi + lo (residual), SW128-swizzled.
__device__ __forceinline__
void st_tile_b(const float4* v, char* smem, uint32_t hiOff, uint32_t loOff, int tid)
{
    #pragma unroll
    for (int i = 0; i < 4; i++) {
        int f = tid + (i << 9);
        int row = f >> 4, c4 = f & 15;
        float4 a = v[i];
        __half2 h01 = __floats2half2_rn(a.x, a.y);
        __half2 h23 = __floats2half2_rn(a.z, a.w);
        float rx = a.x - __low2float(h01);
        float ry = a.y - __high2float(h01);
        float rz = a.z - __low2float(h23);
        float rw = a.w - __high2float(h23);
        uint32_t byte = (row << 7) + (c4 << 3);
        uint32_t sw = byte ^ ((byte >> 3) & 0x70);
        *(uint2*)(smem + hiOff + sw) = make_uint2(*(uint32_t*)&h01, *(uint32_t*)&h23);
        *(uint2*)(smem + loOff + sw) = make_uint2(pack_h2(rx, ry), pack_h2(rz, rw));
    }
}

// ---------------------------------------------------------------------------
// fp16x2 mma.sync GEMM body. NT: C[m,n] = sum_k A[m,k]*B[n,k] over
// (A1,B1,kext1,ld1) then (A2,B2,kext2,ld2). kext may be < ld (masked K).
// MODE: 0 plain, 1 +add residual, 2 tanh(acc/16) w/ col mask
// ---------------------------------------------------------------------------
template<int MODE>
__device__ __forceinline__
void tc_body(const float* __restrict__ A1, const float* __restrict__ B1,
             int k1, int ld1,
             const float* __restrict__ A2, const float* __restrict__ B2,
             int k2, int ld2,
             float* __restrict__ C, const float* __restrict__ add,
             int ldc, int len, int m0, int n0)
{
    extern __shared__ char smem[];
    const uint32_t sb = smem_u32(smem);
    const int tid = threadIdx.x;
    const int lane = tid & 31, wid = tid >> 5;
    const int wm = wid & 3, wn = wid >> 2;

    float acc[2][4][4] = {};

    // ldmatrix lane addressing (128B rows, SW128-style XOR)
    const int a_row = wm * 32 + (lane & 15);
    const uint32_t a_colp = (lane >> 4) << 4;
    const uint32_t a_xor = (uint32_t)(a_row & 7) << 4;
    const int b_row = wn * 32 + ((lane >> 4) << 3) + (lane & 7);
    const uint32_t b_colp = ((lane >> 3) & 1) << 4;
    const uint32_t b_xor = (uint32_t)(b_row & 7) << 4;

    const int n1 = k1 / SLAB;
    const int nslabs = n1 + (A2 ? k2 / SLAB : 0);

    float4 av[4], bv[4];
    // prologue: slab 0
    ld_tile(A1, m0, ld1, 0, av, tid);
    ld_tile(B1, n0, ld1, 0, bv, tid);
    st_tile_a(av, smem, 0, tid);
    st_tile_b(bv, smem, TB, 2*TB, tid);
    __syncthreads();

    for (int s = 0; s < nslabs; s++) {
        const uint32_t bo = (s & 1) * BUFB;
        const uint32_t bn = bo ^ BUFB;
        const bool has = (s + 1) < nslabs;
        const float *An = A1, *Bn = B1; int ldn = ld1, k0n = 0;
        if (has) {
            int sn = s + 1;
            if (sn < n1) { An = A1; Bn = B1; ldn = ld1; k0n = sn * SLAB; }
            else         { An = A2; Bn = B2; ldn = ld2; k0n = (sn - n1) * SLAB; }
        }

        #pragma unroll
        for (int kk = 0; kk < 4; kk++) {
            if (kk == 0 && has) ld_tile(An, m0, ldn, k0n, av, tid);
            if (kk == 2 && has) {
                st_tile_a(av, smem, bn, tid);
                ld_tile(Bn, n0, ldn, k0n, bv, tid);
            }
            if (kk == 3 && has) st_tile_b(bv, smem, bn + TB, bn + 2*TB, tid);

            const uint32_t kb = kk << 5;
            uint32_t bH[8], bL[8];
            {
                uint32_t r = (uint32_t)b_row << 7;
                uint32_t c = (kb + b_colp) ^ b_xor;
                ldsm_x4(bH + 0, sb + bo + TB + r + c);
                ldsm_x4(bH + 4, sb + bo + TB + r + 2048 + c);
                ldsm_x4(bL + 0, sb + bo + 2*TB + r + c);
                ldsm_x4(bL + 4, sb + bo + 2*TB + r + 2048 + c);
            }
            #pragma unroll
            for (int mt = 0; mt < 2; mt++) {
                uint32_t aH[4];
                uint32_t r = (uint32_t)(a_row + mt*16) << 7;
                uint32_t c = (kb + a_colp) ^ a_xor;
                ldsm_x4(aH, sb + bo + r + c);
                #pragma unroll
                for (int nt = 0; nt < 4; nt++) {
                    mma16816(acc[mt][nt], aH, bH + nt*2);
                    mma16816(acc[mt][nt], aH, bL + nt*2);
                }
            }
        }
        if (has) __syncthreads();
    }

    // epilogue
    const int mg = m0 + wm * 32;
    const int ng = n0 + wn * 32;
    const int rq = lane >> 2;
    const int cq = (lane & 3) << 1;
    #pragma unroll
    for (int mt = 0; mt < 2; mt++) {
        #pragma unroll
        for (int nt = 0; nt < 4; nt++) {
            const float* a4 = acc[mt][nt];
            const int r0 = mg + mt*16 + rq, r1 = r0 + 8;
            const int c0 = ng + nt*8 + cq;
            if (MODE == 0) {
                *(float2*)(C + (size_t)r0*ldc + c0) = make_float2(a4[0], a4[1]);
                *(float2*)(C + (size_t)r1*ldc + c0) = make_float2(a4[2], a4[3]);
            } else if (MODE == 1) {
                float2 x0 = *(const float2*)(add + (size_t)r0*ldc + c0);
                float2 x1 = *(const float2*)(add + (size_t)r1*ldc + c0);
                *(float2*)(C + (size_t)r0*ldc + c0) = make_float2(a4[0]+x0.x, a4[1]+x0.y);
                *(float2*)(C + (size_t)r1*ldc + c0) = make_float2(a4[2]+x1.x, a4[3]+x1.y);
            } else {
                float2 v0, v1;
                v0.x = (c0   < len) ? tanhf(a4[0]*TEMP_INV) : 0.f;
                v0.y = (c0+1 < len) ? tanhf(a4[1]*TEMP_INV) : 0.f;
                v1.x = (c0   < len) ? tanhf(a4[2]*TEMP_INV) : 0.f;
                v1.y = (c0+1 < len) ? tanhf(a4[3]*TEMP_INV) : 0.f;
                *(float2*)(C + (size_t)r0*ldc + c0) = v0;
                *(float2*)(C + (size_t)r1*ldc + c0) = v1;
            }
        }
    }
}

// ---------------------------------------------------------------------------
// Stage kernels
// ---------------------------------------------------------------------------
// q/k/v projections: [8192,256] x [256,256], z selects which.
__global__ __launch_bounds__(NT, 1)
void tc_proj_qkv(const float* __restrict__ q, const float* __restrict__ k,
                 const float* __restrict__ v,
                 const float* __restrict__ w_qs, const float* __restrict__ w_ks,
                 const float* __restrict__ w_vs,
                 float* __restrict__ qp, float* __restrict__ kp,
                 float* __restrict__ vp)
{
    const int m0 = blockIdx.y * 128, n0 = blockIdx.x * 128;
    const float* A; const float* W; float* C;
    if      (blockIdx.z == 0) { A = q; W = w_qs; C = qp; }
    else if (blockIdx.z == 1) { A = k; W = w_ks; C = kp; }
    else                      { A = v; W = w_vs; C = vp; }
    tc_body<0>(A, W, DD, DD, nullptr, nullptr, 0, 0, C, nullptr, DD, 0, m0, n0);
}

// Transposed projections: C_b = W (256x256) . X_b^T -> [256,1024] = [d][t]
// z = b*2 + w  (w: 0=qs2, 1=ks2)
__global__ __launch_bounds__(NT, 1)
void tc_projT(const float* __restrict__ q, const float* __restrict__ k,
              const float* __restrict__ w_qs2, const float* __restrict__ w_ks2,
              float* __restrict__ q2t, float* __restrict__ k2t)
{
    const int b = blockIdx.z >> 1, w = blockIdx.z & 1;
    const int m0 = blockIdx.y * 128, n0 = blockIdx.x * 128;
    const float* W = w ? w_ks2 : w_qs2;
    const float* X = (w ? k : q) + (size_t)b*LL*DD;
    float* C = (w ? k2t : q2t) + (size_t)b*DD*LL;
    tc_body<0>(W, X, DD, DD, nullptr, nullptr, 0, 0, C, nullptr, LL, 0, m0, n0);
}

// vwt_b = w_fc @ vp_b^T -> [256,1024]. grid (LL/128, DD/128, BB)
__global__ __launch_bounds__(NT, 1)
void tc_vw(const float* __restrict__ vp, const float* __restrict__ w_fc,
           float* __restrict__ vwt)
{
    const int b = blockIdx.z;
    const int m0 = blockIdx.y * 128, n0 = blockIdx.x * 128;
    tc_body<0>(w_fc, vp + (size_t)b*LL*DD, DD, DD, nullptr, nullptr, 0, 0,
               vwt + (size_t)b*DD*LL, nullptr, LL, 0, m0, n0);
}

// q2f = fa @ q2 (NT with q2t), k2f = fa @ k2. Batch range [b0, b0+nb).
// grid (DD/128, LL/128, nb*2): z = (b-b0)*2 + sel
__global__ __launch_bounds__(NT, 1)
void tc_dual(const float* __restrict__ fa, const float* __restrict__ q2t,
             const float* __restrict__ k2t, const int* __restrict__ lens,
             float* __restrict__ q2f, float* __restrict__ k2f, int b0)
{
    const int b = b0 + (blockIdx.z >> 1), sel = blockIdx.z & 1;
    const int m0 = blockIdx.y * 128, n0 = blockIdx.x * 128;
    const int kmax = ((lens[b] + SLAB - 1) / SLAB) * SLAB;   // fa cols >= len are 0
    const float* A = fa + (size_t)b * LL * LL;
    const float* B = (sel ? k2t : q2t) + (size_t)b * DD * LL;
    float* C = (sel ? k2f : q2f) + (size_t)b * LL * DD;
    tc_body<0>(A, B, kmax, LL, nullptr, nullptr, 0, 0, C, nullptr, DD, 0, m0, n0);
}

// grid (LL/128, LL/128, nb): z = b - b0
__global__ __launch_bounds__(NT, 1)
void tc_logits(const float* __restrict__ qp, const float* __restrict__ kp,
               const float* __restrict__ q2f, const float* __restrict__ k2f,
               const int* __restrict__ lens, float* __restrict__ attn, int b0)
{
    const int b = b0 + blockIdx.z;
    const size_t od = (size_t)b * LL * DD;
    const int m0 = blockIdx.y * 128, n0 = blockIdx.x * 128;
    const int len = lens[b];
    float* out = attn + (size_t)b * LL * LL;
    if (n0 >= len) {
        const float4 z4 = make_float4(0.f, 0.f, 0.f, 0.f);
        for (int i = threadIdx.x; i < 128 * 32; i += NT) {
            int r = i >> 5, c4 = i & 31;
            *(float4*)(out + (size_t)(m0 + r) * LL + n0 + (c4 << 2)) = z4;
        }
        return;
    }
    tc_body<2>(qp + od, kp + od, DD, DD, q2f + od, k2f + od, DD, DD,
               out, nullptr, LL, len, m0, n0);
}

// out_pre = attn @ vw + q. grid (DD/128, LL/128, nb): z = b - b0
__global__ __launch_bounds__(NT, 1)
void tc_av(const float* __restrict__ attn, const float* __restrict__ vwt,
           const int* __restrict__ lens, const float* __restrict__ q,
           float* __restrict__ fc, int b0)
{
    const int b = b0 + blockIdx.z;
    const int m0 = blockIdx.y * 128, n0 = blockIdx.x * 128;
    const int kmax = ((lens[b] + SLAB - 1) / SLAB) * SLAB;
    tc_body<1>(attn + (size_t)b * LL * LL, vwt + (size_t)b * DD * LL, kmax, LL,
               nullptr, nullptr, 0, 0,
               fc + (size_t)b * LL * DD, q + (size_t)b * LL * DD, DD, 0, m0, n0);
}

// ---------------------------------------------------------------------------
// fa kernel: 8 rows per block (1024 blocks), x[b] cached in smem, warp-per-row.
// ---------------------------------------------------------------------------
__global__ __launch_bounds__(256)
void fa_kernel(const float* __restrict__ x, const float* __restrict__ fi,
               const int* __restrict__ lens, float* __restrict__ fa)
{
    __shared__ float xs[LL*FF];
    __shared__ float fis[FF];
    const int blk = blockIdx.x;
    const int b = blk >> 7, rb = blk & 127;
    const int tid = threadIdx.x;
    const float* xb = x + (size_t)b * LL * FF;
    for (int i = tid; i < LL*FF; i += 256) xs[i] = xb[i];
    if (tid < FF) fis[tid] = fi[tid];
    __syncthreads();
    const int len = lens[b];
    const int lane = tid & 31, warp = tid >> 5;

    const int i = rb*8 + warp;
    float xi[FF];
    #pragma unroll
    for (int f = 0; f < FF; f++) xi[f] = xs[i*FF + f];
    float vals[32];
    float m = -INFINITY;
    #pragma unroll
    for (int it = 0; it < 32; it++) {
        const int j = lane + it*32;
        float s = 0.f;
        #pragma unroll
        for (int f = 0; f < FF; f++) s += fabsf(xi[f] - xs[j*FF + f]) * fis[f];
        s = (j < len) ? s : -INFINITY;
        vals[it] = s;
        m = fmaxf(m, s);
    }
    #pragma unroll
    for (int o = 16; o; o >>= 1) m = fmaxf(m, __shfl_xor_sync(~0u, m, o));
    float sum = 0.f;
    #pragma unroll
    for (int it = 0; it < 32; it++) {
        float e = expf(vals[it] - m);
        vals[it] = e;
        sum += e;
    }
    #pragma unroll
    for (int o = 16; o; o >>= 1) sum += __shfl_xor_sync(~0u, sum, o);
    const float inv = 1.f / sum;
    float* outp = fa + ((size_t)b*LL + i) * LL;
    #pragma unroll
    for (int it = 0; it < 32; it++)
        outp[lane + it*32] = vals[it] * inv;
}

// ---------------------------------------------------------------------------
// LayerNorm: warp per row, 8 warps/block, shfl reductions only.
// ---------------------------------------------------------------------------
__global__ __launch_bounds__(256)
void ln_kernel(const float* __restrict__ in, const float* __restrict__ gamma,
               const float* __restrict__ beta, float* __restrict__ out)
{
    __shared__ float gs[DD], bs[DD];
    const int tid = threadIdx.x;
    if (tid < DD) { gs[tid] = gamma[tid]; bs[tid] = beta[tid]; }
    __syncthreads();

    const int lane = tid & 31, warp = tid >> 5;
    const int row = blockIdx.x * 8 + warp;
    const float* rp = in + (size_t)row * DD + lane * 8;

    float4 a0 = *(const float4*)(rp);
    float4 a1 = *(const float4*)(rp + 4);
    float v[8] = {a0.x, a0.y, a0.z, a0.w, a1.x, a1.y, a1.z, a1.w};

    float sum = 0.f;
    #pragma unroll
    for (int i = 0; i < 8; i++) sum += v[i];
    #pragma unroll
    for (int o = 16; o; o >>= 1) sum += __shfl_xor_sync(~0u, sum, o);
    const float mean = sum * (1.0f/DD);

    float vs = 0.f;
    #pragma unroll
    for (int i = 0; i < 8; i++) { v[i] -= mean; vs += v[i] * v[i]; }
    #pragma unroll
    for (int o = 16; o; o >>= 1) vs += __shfl_xor_sync(~0u, vs, o);
    const float rstd = rsqrtf(vs * (1.0f/DD) + LN_EPS);

    float* op = out + (size_t)row * DD + lane * 8;
    const int c = lane * 8;
    float4 o0, o1;
    o0.x = v[0]*rstd*gs[c+0] + bs[c+0];
    o0.y = v[1]*rstd*gs[c+1] + bs[c+1];
    o0.z = v[2]*rstd*gs[c+2] + bs[c+2];
    o0.w = v[3]*rstd*gs[c+3] + bs[c+3];
    o1.x = v[4]*rstd*gs[c+4] + bs[c+4];
    o1.y = v[5]*rstd*gs[c+5] + bs[c+5];
    o1.z = v[6]*rstd*gs[c+6] + bs[c+6];
    o1.w = v[7]*rstd*gs[c+7] + bs[c+7];
    *(float4*)(op)     = o0;
    *(float4*)(op + 4) = o1;
}

// ---------------------------------------------------------------------------
// Host launch. R15 front + back chain split into 2 batch-halves on 2 streams
// (default + s_fa; stream count unchanged from the passing R15 config).
// ---------------------------------------------------------------------------
static cudaStream_t s_fa = nullptr, s_p2 = nullptr, s_qk = nullptr;
static cudaEvent_t  e_root = nullptr, e_fa = nullptr, e_p2 = nullptr,
                    e_qk = nullptr, e_vw = nullptr, e_c1 = nullptr;

extern "C" void kernel_launch(void* const* d_in, const int* in_sizes, int n_in,
                              void* d_out, int out_size)
{
    int li = -1;
    for (int i = 0; i < n_in; i++) if (in_sizes[i] == BB) { li = i; break; }

    const float* q = (const float*)d_in[0];
    const float* k = (const float*)d_in[1];
    const float* v = (const float*)d_in[2];
    const float* x = (const float*)d_in[3];
    const int* lens;
    const float *w_qs, *w_ks, *w_vs, *w_qs2, *w_ks2, *w_fc, *fi, *gamma, *beta;
    if (li == 4) {
        lens  = (const int*)d_in[4];
        w_qs  = (const float*)d_in[5];  w_ks  = (const float*)d_in[6];
        w_vs  = (const float*)d_in[7];  w_qs2 = (const float*)d_in[8];
        w_ks2 = (const float*)d_in[9];  w_fc  = (const float*)d_in[10];
        fi    = (const float*)d_in[11]; gamma = (const float*)d_in[12];
        beta  = (const float*)d_in[13];
    } else {
        w_qs  = (const float*)d_in[4];  w_ks  = (const float*)d_in[5];
        w_vs  = (const float*)d_in[6];  w_qs2 = (const float*)d_in[7];
        w_ks2 = (const float*)d_in[8];  w_fc  = (const float*)d_in[9];
        fi    = (const float*)d_in[10]; gamma = (const float*)d_in[11];
        beta  = (const float*)d_in[12]; lens  = (const int*)d_in[13];
    }

    float *qp, *kp, *vp, *q2t, *k2t, *vwt, *q2f, *k2f, *fc, *fa, *attn_scratch;
    cudaGetSymbolAddress((void**)&qp,  g_qp);
    cudaGetSymbolAddress((void**)&kp,  g_kp);
    cudaGetSymbolAddress((void**)&vp,  g_vp);
    cudaGetSymbolAddress((void**)&q2t, g_q2t);
    cudaGetSymbolAddress((void**)&k2t, g_k2t);
    cudaGetSymbolAddress((void**)&vwt, g_vwt);
    cudaGetSymbolAddress((void**)&q2f, g_q2f);
    cudaGetSymbolAddress((void**)&k2f, g_k2f);
    cudaGetSymbolAddress((void**)&fc,  g_fc);
    cudaGetSymbolAddress((void**)&fa,  g_fa);
    cudaGetSymbolAddress((void**)&attn_scratch, g_attn_scratch);

    const size_t OUT_ELEMS  = (size_t)BB*LL*DD;
    const size_t ATTN_ELEMS = (size_t)BB*LL*LL;
    float* attn = ((size_t)out_size >= OUT_ELEMS + ATTN_ELEMS)
                ? (float*)d_out + OUT_ELEMS
                : attn_scratch;

    if (!s_fa) {
        cudaStreamCreateWithFlags(&s_fa, cudaStreamNonBlocking);
        cudaStreamCreateWithFlags(&s_p2, cudaStreamNonBlocking);
        cudaStreamCreateWithFlags(&s_qk, cudaStreamNonBlocking);
        cudaEventCreateWithFlags(&e_root, cudaEventDisableTiming);
        cudaEventCreateWithFlags(&e_fa,   cudaEventDisableTiming);
        cudaEventCreateWithFlags(&e_p2,   cudaEventDisableTiming);
        cudaEventCreateWithFlags(&e_qk,   cudaEventDisableTiming);
        cudaEventCreateWithFlags(&e_vw,   cudaEventDisableTiming);
        cudaEventCreateWithFlags(&e_c1,   cudaEventDisableTiming);
        cudaFuncSetAttribute(tc_proj_qkv, cudaFuncAttributeMaxDynamicSharedMemorySize, SMEM_DYN);
        cudaFuncSetAttribute(tc_projT,    cudaFuncAttributeMaxDynamicSharedMemorySize, SMEM_DYN);
        cudaFuncSetAttribute(tc_vw,       cudaFuncAttributeMaxDynamicSharedMemorySize, SMEM_DYN);
        cudaFuncSetAttribute(tc_dual,     cudaFuncAttributeMaxDynamicSharedMemorySize, SMEM_DYN);
        cudaFuncSetAttribute(tc_logits,   cudaFuncAttributeMaxDynamicSharedMemorySize, SMEM_DYN);
        cudaFuncSetAttribute(tc_av,       cudaFuncAttributeMaxDynamicSharedMemorySize, SMEM_DYN);
    }

    const int M = BB * LL;  // 8192
    const int HB = BB / 2;  // 4 batches per half
    dim3 blk(NT);
    dim3 blk256(256);

    // ---- Front section: fa, projT, proj_qkv(+vw) concurrent ----
    cudaEventRecord(e_root, 0);
    cudaStreamWaitEvent(s_fa, e_root, 0);
    cudaStreamWaitEvent(s_p2, e_root, 0);
    cudaStreamWaitEvent(s_qk, e_root, 0);

    fa_kernel<<<BB*128, blk256, 0, s_fa>>>(x, fi, lens, fa);
    cudaEventRecord(e_fa, s_fa);

    tc_projT<<<dim3(LL/128, DD/128, 2*BB), blk, SMEM_DYN, s_p2>>>(
        q, k, w_qs2, w_ks2, q2t, k2t);
    cudaEventRecord(e_p2, s_p2);

    tc_proj_qkv<<<dim3(DD/128, M/128, 3), blk, SMEM_DYN, s_qk>>>(
        q, k, v, w_qs, w_ks, w_vs, qp, kp, vp);
    cudaEventRecord(e_qk, s_qk);
    tc_vw<<<dim3(LL/128, DD/128, BB), blk, SMEM_DYN, s_qk>>>(vp, w_fc, vwt);
    cudaEventRecord(e_vw, s_qk);

    // ---- Back chain: two batch-halves on {default, s_fa} ----
    // Half 0 (batches 0..3) on default stream:
    cudaStreamWaitEvent(0, e_fa, 0);
    cudaStreamWaitEvent(0, e_p2, 0);
    tc_dual<<<dim3(DD/128, LL/128, HB*2), blk, SMEM_DYN>>>(fa, q2t, k2t, lens, q2f, k2f, 0);
    cudaStreamWaitEvent(0, e_qk, 0);
    tc_logits<<<dim3(LL/128, LL/128, HB), blk, SMEM_DYN>>>(qp, kp, q2f, k2f, lens, attn, 0);
    cudaStreamWaitEvent(0, e_vw, 0);
    tc_av<<<dim3(DD/128, LL/128, HB), blk, SMEM_DYN>>>(attn, vwt, lens, q, fc, 0);

    // Half 1 (batches 4..7) on s_fa (free after fa_kernel; already ordered
    // behind fa on this stream, so only projT/qk/vw events are needed):
    cudaStreamWaitEvent(s_fa, e_p2, 0);
    tc_dual<<<dim3(DD/128, LL/128, HB*2), blk, SMEM_DYN, s_fa>>>(fa, q2t, k2t, lens, q2f, k2f, HB);
    cudaStreamWaitEvent(s_fa, e_qk, 0);
    tc_logits<<<dim3(LL/128, LL/128, HB), blk, SMEM_DYN, s_fa>>>(qp, kp, q2f, k2f, lens, attn, HB);
    cudaStreamWaitEvent(s_fa, e_vw, 0);
    tc_av<<<dim3(DD/128, LL/128, HB), blk, SMEM_DYN, s_fa>>>(attn, vwt, lens, q, fc, HB);
    cudaEventRecord(e_c1, s_fa);

    // ---- Tail: layernorm joins both halves on default stream ----
    cudaStreamWaitEvent(0, e_c1, 0);
    ln_kernel<<<M/8, blk256>>>(fc, gamma, beta, (float*)d_out);
}